// round 1
// baseline (speedup 1.0000x reference)
#include <cuda_runtime.h>
#include <cstdint>

// Problem constants (fixed by the dataset)
#define Tn 2000
#define Bn 64
#define Vn 163
#define Ln 200
#define Sn 401          // 2*L+1 extended states
#define NEGF (-1e30f)
#define NS 8            // cp.async prefetch depth (power of 2)

// Scratch (no cudaMalloc allowed) — device globals
__device__ float g_lse[Tn * Bn];   // log-sum-exp per (t,b)
__device__ float g_loss[Bn];       // per-utterance NLL

// ---------------------------------------------------------------------------
// Kernel 1: per-row log-sum-exp over vocab. One warp per (t,b) row.
// ---------------------------------------------------------------------------
__global__ void lse_kernel(const float* __restrict__ logits) {
    int warp = (blockIdx.x * blockDim.x + threadIdx.x) >> 5;
    if (warp >= Tn * Bn) return;
    int lane = threadIdx.x & 31;
    const float* p = logits + (size_t)warp * Vn;

    float v[6];
    float m = NEGF;
#pragma unroll
    for (int k = 0; k < 6; k++) {
        int i = lane + 32 * k;
        v[k] = (i < Vn) ? p[i] : NEGF;
        m = fmaxf(m, v[k]);
    }
#pragma unroll
    for (int o = 16; o; o >>= 1) m = fmaxf(m, __shfl_xor_sync(0xffffffffu, m, o));

    float sum = 0.f;
#pragma unroll
    for (int k = 0; k < 6; k++) sum += __expf(v[k] - m);
#pragma unroll
    for (int o = 16; o; o >>= 1) sum += __shfl_xor_sync(0xffffffffu, sum, o);

    if (lane == 0) g_lse[warp] = m + __logf(sum);
}

// ---------------------------------------------------------------------------
// Kernel 2: CTC alpha recursion. One CTA per batch element.
// 416 threads: thread s owns extended-state s (s < 401).
// Logits row for step t (+ its lse) prefetched NS deep with cp.async.
// ---------------------------------------------------------------------------
__global__ __launch_bounds__(416, 1) void ctc_alpha_kernel(
    const float* __restrict__ logits,
    const int*   __restrict__ labels,
    const int*   __restrict__ act_lens,
    const int*   __restrict__ label_lens)
{
    __shared__ float ring[NS][168];      // [0..162] row logits, [163] lse
    __shared__ float abuf[2][Sn + 15];   // alpha double buffer

    const int b = blockIdx.x;
    const int tid = threadIdx.x;
    const int s = tid;
    const int act = act_lens[b];
    const int lab_len = label_lens[b];

    // Per-state static info
    int  e = 0;          // ext[s]: vocab index (0 = blank)
    bool allow = false;  // can use alpha[s-2]
    bool valid = false;  // s < 2*label_len + 1
    if (s < Sn) {
        valid = s < 2 * lab_len + 1;
        if (s & 1) {
            e = labels[b * Ln + ((s - 1) >> 1)];
            if (s >= 3) allow = (e != labels[b * Ln + ((s - 3) >> 1)]);
        }
    }

    const float* base = logits + (size_t)b * Vn;  // element (t,b,v) at base + t*B*V + v

    // --- prefetch prologue: rows 0..NS-1 ---
#pragma unroll
    for (int d = 0; d < NS; d++) {
        if (tid < Vn) {
            uint32_t sa = (uint32_t)__cvta_generic_to_shared(&ring[d][tid]);
            asm volatile("cp.async.ca.shared.global [%0], [%1], 4;"
                         :: "r"(sa), "l"(base + (size_t)d * Bn * Vn + tid));
        } else if (tid == Vn) {
            uint32_t sa = (uint32_t)__cvta_generic_to_shared(&ring[d][Vn]);
            asm volatile("cp.async.ca.shared.global [%0], [%1], 4;"
                         :: "r"(sa), "l"(&g_lse[d * Bn + b]));
        }
        asm volatile("cp.async.commit_group;");
    }

    // --- main serial recursion over time ---
    for (int t = 0; t < act; t++) {
        asm volatile("cp.async.wait_group %0;" :: "n"(NS - 1));
        __syncthreads();

        const float* row = ring[t & (NS - 1)];
        if (s < Sn) {
            float lp = row[e] - row[Vn];      // log-softmax value for ext[s]
            float newv;
            if (t == 0) {
                newv = (s < 2 && valid) ? lp : NEGF;
            } else {
                const float* A = abuf[(t + 1) & 1];
                float a0 = A[s];
                float a1 = (s >= 1) ? A[s - 1] : NEGF;
                float a2 = allow ? A[s - 2] : NEGF;
                float m = fmaxf(a0, fmaxf(a1, a2));
                float sum = __expf(a0 - m) + __expf(a1 - m) + __expf(a2 - m);
                newv = m + __logf(sum) + lp;
                if (!valid) newv = NEGF;
            }
            abuf[t & 1][s] = newv;
        }
        __syncthreads();   // everyone done with ring slot t and old alpha

        // prefetch row t+NS into the slot just freed (clamped; never consumed if >= act)
        int tl = t + NS; if (tl > Tn - 1) tl = Tn - 1;
        const int slot = t & (NS - 1);
        if (tid < Vn) {
            uint32_t sa = (uint32_t)__cvta_generic_to_shared(&ring[slot][tid]);
            asm volatile("cp.async.ca.shared.global [%0], [%1], 4;"
                         :: "r"(sa), "l"(base + (size_t)tl * Bn * Vn + tid));
        } else if (tid == Vn) {
            uint32_t sa = (uint32_t)__cvta_generic_to_shared(&ring[slot][Vn]);
            asm volatile("cp.async.ca.shared.global [%0], [%1], 4;"
                         :: "r"(sa), "l"(&g_lse[tl * Bn + b]));
        }
        asm volatile("cp.async.commit_group;");
    }

    // drain outstanding copies before exit
    asm volatile("cp.async.wait_group 0;");

    if (tid == 0) {
        const float* A = abuf[(act - 1) & 1];   // act >= 1000 always
        int end = 2 * lab_len;                  // lab_len >= 100 > 0
        float al = A[end];
        float ap = A[end - 1];
        float m = fmaxf(al, ap);
        g_loss[b] = -(m + __logf(__expf(al - m) + __expf(ap - m)));
    }
}

// ---------------------------------------------------------------------------
// Kernel 3: total = sum(losses) / sum(act_lens)
// ---------------------------------------------------------------------------
__global__ void finalize_kernel(const int* __restrict__ act_lens,
                                float* __restrict__ out)
{
    int tid = threadIdx.x;  // 64 threads
    float l = g_loss[tid];
    float a = (float)act_lens[tid];
#pragma unroll
    for (int o = 16; o; o >>= 1) {
        l += __shfl_xor_sync(0xffffffffu, l, o);
        a += __shfl_xor_sync(0xffffffffu, a, o);
    }
    __shared__ float sl[2], sa[2];
    if ((tid & 31) == 0) { sl[tid >> 5] = l; sa[tid >> 5] = a; }
    __syncthreads();
    if (tid == 0) out[0] = (sl[0] + sl[1]) / (sa[0] + sa[1]);
}

// ---------------------------------------------------------------------------
extern "C" void kernel_launch(void* const* d_in, const int* in_sizes, int n_in,
                              void* d_out, int out_size)
{
    const float* logits     = (const float*)d_in[0];  // [T, B, V]
    const int*   labels     = (const int*)d_in[1];    // [B, L]
    const int*   act_lens   = (const int*)d_in[2];    // [B]
    const int*   label_lens = (const int*)d_in[3];    // [B]

    // 1 warp per (t,b) row; 8 warps per block
    lse_kernel<<<(Tn * Bn + 7) / 8, 256>>>(logits);
    ctc_alpha_kernel<<<Bn, 416>>>(logits, labels, act_lens, label_lens);
    finalize_kernel<<<1, 64>>>(act_lens, (float*)d_out);
}